// round 5
// baseline (speedup 1.0000x reference)
#include <cuda_runtime.h>
#include <cuda_bf16.h>
#include <cstdint>

// MultiGridAgentEncoder: fused slot-gather + relu(x @ W + b)
// bf16 split-precision GEMM via mma.sync.m16n8k16 (HMMA), fp32 accum.
// R5: M=64 x N=128 tiles, 256 thr, 107.5KB smem -> 2 CTAs/SM for phase overlap.

#define NTHREADS 256
#define PITCH_B  272          // bytes per K-row (128 bf16 + 16B pad), ldmatrix conflict-free
#define AF_PITCH 209          // floats per row in AF staging buffer

// smem byte offsets
#define SM_A_HI  0            // 64 * 272 = 17408
#define SM_A_LO  17408        // ends 34816
#define SM_B_HI  34816        // 128 * 272 = 34816, ends 69632
#define SM_B_LO  69632        // ends 104448
#define SM_AF    34816        // AF: 64 * 209 * 4 = 53504, ends 88320 (inside B region, used pre-B)
#define SM_SLOT  104448       // [s][r]: 8 * 64 ints = 2048
#define SM_BIAS  106496       // 256 floats = 1024
#define SMEM_BYTES 107520

// Pre-split W (filled once by w_split): [n][k] bf16, k padded to 128
__device__ __nv_bfloat16 g_Whi[256 * 128];
__device__ __nv_bfloat16 g_Wlo[256 * 128];

__global__ void w_split(const float* __restrict__ W) {
    const int k = blockIdx.x;        // 0..127
    const int n = threadIdx.x;       // 0..255
    float w = (k < 117) ? W[k * 256 + n] : 0.0f;
    __nv_bfloat16 h = __float2bfloat16(w);
    g_Whi[n * 128 + k] = h;
    g_Wlo[n * 128 + k] = __float2bfloat16(w - __bfloat162float(h));
}

static __device__ __forceinline__ uint32_t smem_u32(const void* p) {
    uint32_t a;
    asm("{ .reg .u64 t; cvta.to.shared.u64 t, %1; cvt.u32.u64 %0, t; }" : "=r"(a) : "l"(p));
    return a;
}
static __device__ __forceinline__ void ldsm_x4(uint32_t& r0, uint32_t& r1, uint32_t& r2,
                                               uint32_t& r3, uint32_t addr) {
    asm volatile("ldmatrix.sync.aligned.m8n8.x4.shared.b16 {%0,%1,%2,%3}, [%4];"
                 : "=r"(r0), "=r"(r1), "=r"(r2), "=r"(r3) : "r"(addr));
}
static __device__ __forceinline__ void mma_bf16(float* c, const uint32_t* a,
                                                uint32_t b0, uint32_t b1) {
    asm volatile(
        "mma.sync.aligned.m16n8k16.row.col.f32.bf16.bf16.f32 "
        "{%0,%1,%2,%3}, {%4,%5,%6,%7}, {%8,%9}, {%0,%1,%2,%3};"
        : "+f"(c[0]), "+f"(c[1]), "+f"(c[2]), "+f"(c[3])
        : "r"(a[0]), "r"(a[1]), "r"(a[2]), "r"(a[3]), "r"(b0), "r"(b1));
}
static __device__ __forceinline__ void splitw(float v, __nv_bfloat16& h, __nv_bfloat16& l) {
    h = __float2bfloat16(v);
    l = __float2bfloat16(v - __bfloat162float(h));
}

__global__ __launch_bounds__(256, 2)
void mg_enc_hmma(const float* __restrict__ qpos, const float* __restrict__ qdir,
                 const float* __restrict__ qab,  const float* __restrict__ qcar,
                 const float* __restrict__ qst,
                 const float* __restrict__ apos, const float* __restrict__ adir,
                 const float* __restrict__ aab,  const float* __restrict__ acar,
                 const float* __restrict__ ast,
                 const int*   __restrict__ color,
                 const float* __restrict__ bias,
                 float* __restrict__ out)
{
    extern __shared__ __align__(128) char smem[];
    const uint32_t sbase = smem_u32(smem);
    const int tid = threadIdx.x;
    const int wid = tid >> 5, lid = tid & 31;
    const int row0 = (blockIdx.x >> 1) * 64;        // 64-row tile
    const int nbase = (blockIdx.x & 1) * 128;       // N half: cols nbase..nbase+127

    // ================= Phase 1: bias + slots + coalesced AF stage + query =================
    ((float*)(smem + SM_BIAS))[tid] = bias[tid];

    // slot assignment: thread m handles row row0+m; table layout [s][r]
    if (tid < 64) {
        const int4* cp = (const int4*)(color + (size_t)(row0 + tid) * 16);
        int4 v0 = cp[0], v1 = cp[1], v2 = cp[2], v3 = cp[3];
        int cols[16] = { v0.x, v0.y, v0.z, v0.w, v1.x, v1.y, v1.z, v1.w,
                         v2.x, v2.y, v2.z, v2.w, v3.x, v3.y, v3.z, v3.w };
        int sa[8];
#pragma unroll
        for (int s = 0; s < 8; s++) sa[s] = -1;
        int sg = 0, sy = 0;
#pragma unroll
        for (int n = 0; n < 16; n++) {
            int c = cols[n];
            if (c == 5) { if (sg < 4) sa[sg] = n; sg++; }          // grey -> slots 0..3
            else if (c == 4) { if (sy < 4) sa[4 + sy] = n; sy++; } // yellow -> slots 4..7
        }
        int* sl = (int*)(smem + SM_SLOT);
#pragma unroll
        for (int s = 0; s < 8; s++) sl[s * 64 + tid] = sa[s];
    }

    // AF stage: 4 threads per row (64 rows x 4 = 256), coalesced float4 loads
    {
        const int r = tid >> 2, p = tid & 3;
        const size_t grow = (size_t)(row0 + r);
        float* af = (float*)(smem + SM_AF) + r * AF_PITCH;
        const int a0 = 4 * p;
        {
            const float4* s4 = (const float4*)(apos + grow * 32) + p * 2;
            float4 u = s4[0], v = s4[1];
            af[(a0+0)*13+0]=u.x; af[(a0+0)*13+1]=u.y; af[(a0+1)*13+0]=u.z; af[(a0+1)*13+1]=u.w;
            af[(a0+2)*13+0]=v.x; af[(a0+2)*13+1]=v.y; af[(a0+3)*13+0]=v.z; af[(a0+3)*13+1]=v.w;
        }
        {
            const float4* s4 = (const float4*)(adir + grow * 64) + p * 4;
#pragma unroll
            for (int i = 0; i < 4; i++) {
                float4 u = s4[i];
                float* d = af + (a0 + i) * 13 + 2;
                d[0]=u.x; d[1]=u.y; d[2]=u.z; d[3]=u.w;
            }
        }
        {
            const float4* s4 = (const float4*)(aab + grow * 32) + p * 2;
            float4 u = s4[0], v = s4[1];
            af[(a0+0)*13+6]=u.x; af[(a0+0)*13+7]=u.y; af[(a0+1)*13+6]=u.z; af[(a0+1)*13+7]=u.w;
            af[(a0+2)*13+6]=v.x; af[(a0+2)*13+7]=v.y; af[(a0+3)*13+6]=v.z; af[(a0+3)*13+7]=v.w;
        }
        {
            const float4* s4 = (const float4*)(acar + grow * 32) + p * 2;
            float4 u = s4[0], v = s4[1];
            af[(a0+0)*13+8]=u.x; af[(a0+0)*13+9]=u.y; af[(a0+1)*13+8]=u.z; af[(a0+1)*13+9]=u.w;
            af[(a0+2)*13+8]=v.x; af[(a0+2)*13+9]=v.y; af[(a0+3)*13+8]=v.z; af[(a0+3)*13+9]=v.w;
        }
        {
            const float4* s4 = (const float4*)(ast + grow * 48) + p * 3;
            float t[12];
            *(float4*)(t + 0) = s4[0];
            *(float4*)(t + 4) = s4[1];
            *(float4*)(t + 8) = s4[2];
#pragma unroll
            for (int i = 0; i < 12; i++)
                af[(a0 + i / 3) * 13 + 10 + (i % 3)] = t[i];
        }
    }

    // query features -> A rows k=0..12, plus K-pad (thread t handles row t)
    if (tid < 64) {
        const size_t row = (size_t)(row0 + tid);
        float q[13];
        *(float2*)(q + 0) = *(const float2*)(qpos + row * 2);
        *(float4*)(q + 2) = *(const float4*)(qdir + row * 4);
        *(float2*)(q + 6) = *(const float2*)(qab  + row * 2);
        *(float2*)(q + 8) = *(const float2*)(qcar + row * 2);
        q[10] = qst[row * 3 + 0]; q[11] = qst[row * 3 + 1]; q[12] = qst[row * 3 + 2];
        char* ah = smem + SM_A_HI + tid * PITCH_B;
        char* al = smem + SM_A_LO + tid * PITCH_B;
#pragma unroll
        for (int k = 0; k < 13; k++) {
            __nv_bfloat16 h, l; splitw(q[k], h, l);
            *(__nv_bfloat16*)(ah + k * 2) = h;
            *(__nv_bfloat16*)(al + k * 2) = l;
        }
#pragma unroll
        for (int k = 117; k < 128; k++) {
            *(__nv_bfloat16*)(ah + k * 2) = __nv_bfloat16(0.0f);
            *(__nv_bfloat16*)(al + k * 2) = __nv_bfloat16(0.0f);
        }
    }
    __syncthreads();

    // ================= Phase 2: scatter AF -> A tiles (k=13..116) =================
    {
        const int r = tid & 63;
        const int jb = tid >> 6;                              // 0..3
        const int* sl = (const int*)(smem + SM_SLOT);
        const float* af = (const float*)(smem + SM_AF) + r * AF_PITCH;
        char* ah = smem + SM_A_HI + r * PITCH_B;
        char* al = smem + SM_A_LO + r * PITCH_B;
#pragma unroll
        for (int it = 0; it < 26; it++) {
            const int j = it * 4 + jb;                        // 0..103
            const int s = j / 13, f = j - s * 13;
            const int a = sl[s * 64 + r];
            const float v = (a >= 0) ? af[a * 13 + f] : 0.0f;
            __nv_bfloat16 h, l; splitw(v, h, l);
            *(__nv_bfloat16*)(ah + (13 + j) * 2) = h;
            *(__nv_bfloat16*)(al + (13 + j) * 2) = l;
        }
    }
    __syncthreads();

    // ================= Phase 3: B copy (this N half, pre-split bf16, uint4) =================
    {
        const uint4* WH = (const uint4*)g_Whi;   // [256][16]
        const uint4* WL = (const uint4*)g_Wlo;
#pragma unroll
        for (int it = 0; it < 8; it++) {
            const int idx = it * 256 + tid;       // 0..2047
            const int nl = idx >> 4, c = idx & 15;
            const int n = nbase + nl;
            *(uint4*)(smem + SM_B_HI + nl * PITCH_B + c * 16) = WH[n * 16 + c];
            *(uint4*)(smem + SM_B_LO + nl * PITCH_B + c * 16) = WL[n * 16 + c];
        }
    }
    __syncthreads();

    // ================= Phase 4: MMA (8 warps, 2x4 grid, warp tile 32x32) =================
    const int warp_m = wid >> 2, warp_n = wid & 3;
    float acc[2][4][4];
#pragma unroll
    for (int mt = 0; mt < 2; mt++)
#pragma unroll
        for (int nt = 0; nt < 4; nt++)
#pragma unroll
            for (int e = 0; e < 4; e++) acc[mt][nt][e] = 0.0f;

    const uint32_t lrow = lid & 15, lhalf = (uint32_t)lid >> 4;
    const uint32_t a_lane = (warp_m * 32 + lrow) * PITCH_B + lhalf * 16;
    const uint32_t b_lane = (warp_n * 32 + lrow) * PITCH_B + lhalf * 16;

    const uint32_t passA[3] = { sbase + SM_A_HI, sbase + SM_A_HI, sbase + SM_A_LO };
    const uint32_t passB[3] = { sbase + SM_B_HI, sbase + SM_B_LO, sbase + SM_B_HI };

    for (int pass = 0; pass < 3; pass++) {
        const uint32_t Ab = passA[pass] + a_lane;
        const uint32_t Bb = passB[pass] + b_lane;
#pragma unroll 4
        for (int ks = 0; ks < 8; ks++) {
            const uint32_t koff = ks * 32;
            uint32_t a[2][4];
#pragma unroll
            for (int mt = 0; mt < 2; mt++)
                ldsm_x4(a[mt][0], a[mt][1], a[mt][2], a[mt][3],
                        Ab + mt * (16 * PITCH_B) + koff);
            uint32_t b[2][4];
#pragma unroll
            for (int nb = 0; nb < 2; nb++)
                ldsm_x4(b[nb][0], b[nb][1], b[nb][2], b[nb][3],
                        Bb + nb * (16 * PITCH_B) + koff);
#pragma unroll
            for (int mt = 0; mt < 2; mt++)
#pragma unroll
                for (int nb = 0; nb < 2; nb++) {
                    mma_bf16(acc[mt][nb * 2 + 0], a[mt], b[nb][0], b[nb][2]);
                    mma_bf16(acc[mt][nb * 2 + 1], a[mt], b[nb][1], b[nb][3]);
                }
        }
    }

    // ================= Epilogue: bias + relu + direct stores =================
    const float* biass = (const float*)(smem + SM_BIAS);
    const int rbase = row0 + warp_m * 32 + (lid >> 2);
    const int cbase = nbase + warp_n * 32 + (lid & 3) * 2;
#pragma unroll
    for (int mt = 0; mt < 2; mt++) {
#pragma unroll
        for (int nt = 0; nt < 4; nt++) {
            const int c = cbase + nt * 8;
            const float b0 = biass[c], b1 = biass[c + 1];
            float2 v0, v1;
            v0.x = fmaxf(acc[mt][nt][0] + b0, 0.0f);
            v0.y = fmaxf(acc[mt][nt][1] + b1, 0.0f);
            v1.x = fmaxf(acc[mt][nt][2] + b0, 0.0f);
            v1.y = fmaxf(acc[mt][nt][3] + b1, 0.0f);
            const size_t r0 = (size_t)(rbase + mt * 16);
            *(float2*)(out + r0 * 256 + c)       = v0;
            *(float2*)(out + (r0 + 8) * 256 + c) = v1;
        }
    }
}

extern "C" void kernel_launch(void* const* d_in, const int* in_sizes, int n_in,
                              void* d_out, int out_size)
{
    const float* qpos  = (const float*)d_in[0];
    const float* qdir  = (const float*)d_in[1];
    const float* qab   = (const float*)d_in[2];
    const float* qcar  = (const float*)d_in[3];
    const float* qst   = (const float*)d_in[4];
    const float* apos  = (const float*)d_in[5];
    const float* adir  = (const float*)d_in[6];
    const float* aab   = (const float*)d_in[7];
    const float* acar  = (const float*)d_in[8];
    const float* ast   = (const float*)d_in[9];
    const int*   color = (const int*)  d_in[10];
    const float* W     = (const float*)d_in[11];
    const float* bias  = (const float*)d_in[12];
    float* out = (float*)d_out;

    w_split<<<128, 256>>>(W);

    cudaFuncSetAttribute(mg_enc_hmma,
                         cudaFuncAttributeMaxDynamicSharedMemorySize, SMEM_BYTES);
    mg_enc_hmma<<<4096, NTHREADS, SMEM_BYTES>>>(
        qpos, qdir, qab, qcar, qst,
        apos, adir, aab, acar, ast,
        color, bias, out);
}

// round 7
// speedup vs baseline: 1.0729x; 1.0729x over previous
#include <cuda_runtime.h>
#include <cuda_bf16.h>
#include <cstdint>

// MultiGridAgentEncoder: fused slot-gather + relu(x @ W + b)
// R7: persistent CTAs (grid=148), M=64 x N=256 tile per iteration,
// cp.async prefetch of raw features overlapped with split-bf16 HMMA.
// Fix vs R6: slot table is SIGNED char (aarch64 plain char is unsigned).

#define NTHREADS 512
#define GRID     148
#define NTILES   2048
#define TSTRIDE  148
#define PITCH    272          // bytes per K-row (128 bf16 + 16B pad), ldmatrix conflict-free

// smem byte offsets
#define SM_A_HI  0            // 64*272 = 17408
#define SM_A_LO  17408        // ends 34816
#define SM_B_HI  34816        // 256*272 = 69632, ends 104448
#define SM_B_LO  104448       // ends 174080
#define SM_AF    174080       // 64 rows * 832B (208 floats) = 53248, ends 227328
#define SM_QRAW  227328       // 64 rows * 64B = 4096, ends 231424
#define SM_SLOT  231424       // 8*64 bytes = 512, ends 231936
#define SMEM_BYTES 231936

// Pre-split W (filled once by w_split): [n][k] bf16, k padded to 128
__device__ __nv_bfloat16 g_Whi[256 * 128];
__device__ __nv_bfloat16 g_Wlo[256 * 128];

__global__ void w_split(const float* __restrict__ W) {
    const int k = blockIdx.x;        // 0..127
    const int n = threadIdx.x;       // 0..255
    float w = (k < 117) ? W[k * 256 + n] : 0.0f;
    __nv_bfloat16 h = __float2bfloat16(w);
    g_Whi[n * 128 + k] = h;
    g_Wlo[n * 128 + k] = __float2bfloat16(w - __bfloat162float(h));
}

static __device__ __forceinline__ uint32_t smem_u32(const void* p) {
    uint32_t a;
    asm("{ .reg .u64 t; cvta.to.shared.u64 t, %1; cvt.u32.u64 %0, t; }" : "=r"(a) : "l"(p));
    return a;
}
static __device__ __forceinline__ void cpa16(uint32_t dst, const void* src) {
    asm volatile("cp.async.cg.shared.global [%0], [%1], 16;" :: "r"(dst), "l"(src));
}
static __device__ __forceinline__ void cpa8(uint32_t dst, const void* src) {
    asm volatile("cp.async.ca.shared.global [%0], [%1], 8;" :: "r"(dst), "l"(src));
}
static __device__ __forceinline__ void cpa4(uint32_t dst, const void* src) {
    asm volatile("cp.async.ca.shared.global [%0], [%1], 4;" :: "r"(dst), "l"(src));
}
static __device__ __forceinline__ void ldsm_x4(uint32_t& r0, uint32_t& r1, uint32_t& r2,
                                               uint32_t& r3, uint32_t addr) {
    asm volatile("ldmatrix.sync.aligned.m8n8.x4.shared.b16 {%0,%1,%2,%3}, [%4];"
                 : "=r"(r0), "=r"(r1), "=r"(r2), "=r"(r3) : "r"(addr));
}
static __device__ __forceinline__ void mma_bf16(float* c, const uint32_t* a,
                                                uint32_t b0, uint32_t b1) {
    asm volatile(
        "mma.sync.aligned.m16n8k16.row.col.f32.bf16.bf16.f32 "
        "{%0,%1,%2,%3}, {%4,%5,%6,%7}, {%8,%9}, {%0,%1,%2,%3};"
        : "+f"(c[0]), "+f"(c[1]), "+f"(c[2]), "+f"(c[3])
        : "r"(a[0]), "r"(a[1]), "r"(a[2]), "r"(a[3]), "r"(b0), "r"(b1));
}
static __device__ __forceinline__ void splitw(float v, __nv_bfloat16& h, __nv_bfloat16& l) {
    h = __float2bfloat16(v);
    l = __float2bfloat16(v - __bfloat162float(h));
}

// issue cp.async for tile's raw agent features + query rows
static __device__ __forceinline__ void issue_tile_cpasync(
    uint32_t sbase, int tid, int row0,
    const float* qpos, const float* qdir, const float* qab, const float* qcar,
    const float* qst,  const float* apos, const float* adir, const float* aab,
    const float* acar, const float* ast)
{
    // AF row layout (floats): apos@0(32) adir@32(64) aab@96(32) acar@128(32) ast@160(48)
    {   // apos: 512 chunks of 16B
        const int r = tid >> 3, c = tid & 7;
        cpa16(sbase + SM_AF + r * 832 + c * 16, apos + (size_t)(row0 + r) * 32 + c * 4);
    }
#pragma unroll
    for (int it = 0; it < 2; it++) {   // adir: 1024 chunks
        const int idx = it * 512 + tid;
        const int r = idx >> 4, c = idx & 15;
        cpa16(sbase + SM_AF + r * 832 + 128 + c * 16, adir + (size_t)(row0 + r) * 64 + c * 4);
    }
    {   // aab: 512
        const int r = tid >> 3, c = tid & 7;
        cpa16(sbase + SM_AF + r * 832 + 384 + c * 16, aab + (size_t)(row0 + r) * 32 + c * 4);
    }
    {   // acar: 512
        const int r = tid >> 3, c = tid & 7;
        cpa16(sbase + SM_AF + r * 832 + 512 + c * 16, acar + (size_t)(row0 + r) * 32 + c * 4);
    }
#pragma unroll
    for (int it = 0; it < 2; it++) {   // ast: 768 chunks
        const int idx = it * 512 + tid;
        if (idx < 768) {
            const int r = idx / 12, c = idx % 12;
            cpa16(sbase + SM_AF + r * 832 + 640 + c * 16, ast + (size_t)(row0 + r) * 48 + c * 4);
        }
    }
    if (tid < 64) {   // query row: QRAW floats [0..3]=qdir [4..5]=qpos [6..7]=qab [8..9]=qcar [10..12]=qst
        const size_t row = (size_t)(row0 + tid);
        const uint32_t qb = sbase + SM_QRAW + tid * 64;
        cpa16(qb + 0,  qdir + row * 4);
        cpa8 (qb + 16, qpos + row * 2);
        cpa8 (qb + 24, qab  + row * 2);
        cpa8 (qb + 32, qcar + row * 2);
        cpa4 (qb + 40, qst + row * 3);
        cpa4 (qb + 44, qst + row * 3 + 1);
        cpa4 (qb + 48, qst + row * 3 + 2);
    }
    asm volatile("cp.async.commit_group;");
}

__global__ __launch_bounds__(512, 1)
void mg_enc_hmma(const float* __restrict__ qpos, const float* __restrict__ qdir,
                 const float* __restrict__ qab,  const float* __restrict__ qcar,
                 const float* __restrict__ qst,
                 const float* __restrict__ apos, const float* __restrict__ adir,
                 const float* __restrict__ aab,  const float* __restrict__ acar,
                 const float* __restrict__ ast,
                 const int*   __restrict__ color,
                 const float* __restrict__ bias,
                 float* __restrict__ out)
{
    extern __shared__ __align__(128) char smem[];
    const uint32_t sbase = smem_u32(smem);
    const int tid = threadIdx.x;
    const int wid = tid >> 5, lid = tid & 31;

    // ---------------- prologue ----------------
    // B tiles: copy pre-split bf16 W into smem once (cp.async)
#pragma unroll
    for (int it = 0; it < 8; it++) {
        const int idx = it * 512 + tid;
        const int n = idx >> 4, c = idx & 15;
        cpa16(sbase + SM_B_HI + n * PITCH + c * 16, (const char*)g_Whi + n * 256 + c * 16);
        cpa16(sbase + SM_B_LO + n * PITCH + c * 16, (const char*)g_Wlo + n * 256 + c * 16);
    }
    asm volatile("cp.async.commit_group;");

    int t = blockIdx.x;                      // first tile for this CTA
    // prefetch tile t raw features + query
    issue_tile_cpasync(sbase, tid, t * 64, qpos, qdir, qab, qcar, qst,
                       apos, adir, aab, acar, ast);
    // prefetch color rows for tile t into registers
    int4 c0, c1, c2, c3;
    if (tid < 64) {
        const int4* cp = (const int4*)(color + (size_t)(t * 64 + tid) * 16);
        c0 = cp[0]; c1 = cp[1]; c2 = cp[2]; c3 = cp[3];
    }

    // scatter-thread invariants: thread owns fixed k, 16 rows (r = i*4 + rq)
    const int k  = tid & 127;
    const int rq = tid >> 7;
    int qidx = 0, aoff = 0, amult = 0, sslot = 0;
    if (k < 13) {
        qidx = (k < 2) ? k + 4 : ((k < 6) ? k - 2 : k);
    } else if (k < 117) {
        const int j = k - 13;
        sslot = j / 13;
        const int f = j - sslot * 13;
        if (f < 2)       { aoff = 0   + f;      amult = 2; }
        else if (f < 6)  { aoff = 32  + f - 2;  amult = 4; }
        else if (f < 8)  { aoff = 96  + f - 6;  amult = 2; }
        else if (f < 10) { aoff = 128 + f - 8;  amult = 2; }
        else             { aoff = 160 + f - 10; amult = 3; }
    } else {
        // zero-pad K rows 117..127 once (A buffer persists across tiles)
#pragma unroll
        for (int i = 0; i < 16; i++) {
            const int r = i * 4 + rq;
            *(__nv_bfloat16*)(smem + SM_A_HI + r * PITCH + k * 2) = __nv_bfloat16(0.0f);
            *(__nv_bfloat16*)(smem + SM_A_LO + r * PITCH + k * 2) = __nv_bfloat16(0.0f);
        }
    }

    // MMA invariants
    const int wm = wid >> 3, wn = wid & 7;          // 2 x 8 warp grid, warp tile 32x32
    const uint32_t lrow = lid & 15, lhalf = (uint32_t)lid >> 4;
    const uint32_t a_lane = (wm * 32 + lrow) * PITCH + lhalf * 16;
    const uint32_t b_lane = (wn * 32 + lrow) * PITCH + lhalf * 16;
    const uint32_t AHb = sbase + SM_A_HI + a_lane;
    const uint32_t ALb = sbase + SM_A_LO + a_lane;
    const uint32_t BHb = sbase + SM_B_HI + b_lane;
    const uint32_t BLb = sbase + SM_B_LO + b_lane;

    // bias for this thread's 8 output columns
    float be[4], bo[4];
#pragma unroll
    for (int nt = 0; nt < 4; nt++) {
        const int c = wn * 32 + (lid & 3) * 2 + nt * 8;
        be[nt] = bias[c];
        bo[nt] = bias[c + 1];
    }

    signed char* const slotb = (signed char*)(smem + SM_SLOT);   // FIX: explicit signed
    const float* const aff  = (const float*)(smem + SM_AF);
    const float* const qrf  = (const float*)(smem + SM_QRAW);

    // ---------------- persistent tile loop ----------------
    for (; t < NTILES; t += TSTRIDE) {
        asm volatile("cp.async.wait_group 0;");
        __syncthreads();                       // AF/QRAW(t) ready; prev MMA done

        // slot assignment from prefetched color regs
        if (tid < 64) {
            int cols[16] = { c0.x, c0.y, c0.z, c0.w, c1.x, c1.y, c1.z, c1.w,
                             c2.x, c2.y, c2.z, c2.w, c3.x, c3.y, c3.z, c3.w };
            signed char sa[8];
#pragma unroll
            for (int s = 0; s < 8; s++) sa[s] = -1;
            int sg = 0, sy = 0;
#pragma unroll
            for (int n = 0; n < 16; n++) {
                int c = cols[n];
                if (c == 5) { if (sg < 4) sa[sg] = (signed char)n; sg++; }
                else if (c == 4) { if (sy < 4) sa[4 + sy] = (signed char)n; sy++; }
            }
#pragma unroll
            for (int s = 0; s < 8; s++) slotb[s * 64 + tid] = sa[s];
        }
        __syncthreads();                       // slot table visible

        // scatter: build A tile (bf16 hi/lo), k fixed per thread, 16 rows
        if (k < 13) {
#pragma unroll
            for (int i = 0; i < 16; i++) {
                const int r = i * 4 + rq;
                const float v = qrf[r * 16 + qidx];
                __nv_bfloat16 h, l; splitw(v, h, l);
                *(__nv_bfloat16*)(smem + SM_A_HI + r * PITCH + k * 2) = h;
                *(__nv_bfloat16*)(smem + SM_A_LO + r * PITCH + k * 2) = l;
            }
        } else if (k < 117) {
#pragma unroll
            for (int i = 0; i < 16; i++) {
                const int r = i * 4 + rq;
                const int a = (int)slotb[sslot * 64 + r];
                const float v = (a >= 0) ? aff[r * 208 + aoff + a * amult] : 0.0f;
                __nv_bfloat16 h, l; splitw(v, h, l);
                *(__nv_bfloat16*)(smem + SM_A_HI + r * PITCH + k * 2) = h;
                *(__nv_bfloat16*)(smem + SM_A_LO + r * PITCH + k * 2) = l;
            }
        }

        // prefetch color for next tile (regs)
        const int tn = t + TSTRIDE;
        if (tn < NTILES && tid < 64) {
            const int4* cp = (const int4*)(color + (size_t)(tn * 64 + tid) * 16);
            c0 = cp[0]; c1 = cp[1]; c2 = cp[2]; c3 = cp[3];
        }
        __syncthreads();                       // A complete; AF/QRAW free

        // prefetch next tile's raw features (overlaps with MMA below)
        if (tn < NTILES)
            issue_tile_cpasync(sbase, tid, tn * 64, qpos, qdir, qab, qcar, qst,
                               apos, adir, aab, acar, ast);

        // ---- MMA: merged pass (AH*BH + AH*BL) then pass3 (AL*BH) ----
        float acc[2][4][4];
#pragma unroll
        for (int mt = 0; mt < 2; mt++)
#pragma unroll
            for (int nt = 0; nt < 4; nt++)
#pragma unroll
                for (int e = 0; e < 4; e++) acc[mt][nt][e] = 0.0f;

#pragma unroll
        for (int ks = 0; ks < 8; ks++) {
            const uint32_t koff = ks * 32;
            uint32_t a[2][4], bh[2][4], bl[2][4];
#pragma unroll
            for (int mt = 0; mt < 2; mt++)
                ldsm_x4(a[mt][0], a[mt][1], a[mt][2], a[mt][3],
                        AHb + mt * (16 * PITCH) + koff);
#pragma unroll
            for (int nb = 0; nb < 2; nb++) {
                ldsm_x4(bh[nb][0], bh[nb][1], bh[nb][2], bh[nb][3],
                        BHb + nb * (16 * PITCH) + koff);
                ldsm_x4(bl[nb][0], bl[nb][1], bl[nb][2], bl[nb][3],
                        BLb + nb * (16 * PITCH) + koff);
            }
#pragma unroll
            for (int mt = 0; mt < 2; mt++)
#pragma unroll
                for (int nb = 0; nb < 2; nb++) {
                    mma_bf16(acc[mt][nb * 2 + 0], a[mt], bh[nb][0], bh[nb][2]);
                    mma_bf16(acc[mt][nb * 2 + 1], a[mt], bh[nb][1], bh[nb][3]);
                    mma_bf16(acc[mt][nb * 2 + 0], a[mt], bl[nb][0], bl[nb][2]);
                    mma_bf16(acc[mt][nb * 2 + 1], a[mt], bl[nb][1], bl[nb][3]);
                }
        }
#pragma unroll
        for (int ks = 0; ks < 8; ks++) {
            const uint32_t koff = ks * 32;
            uint32_t a[2][4], bh[2][4];
#pragma unroll
            for (int mt = 0; mt < 2; mt++)
                ldsm_x4(a[mt][0], a[mt][1], a[mt][2], a[mt][3],
                        ALb + mt * (16 * PITCH) + koff);
#pragma unroll
            for (int nb = 0; nb < 2; nb++)
                ldsm_x4(bh[nb][0], bh[nb][1], bh[nb][2], bh[nb][3],
                        BHb + nb * (16 * PITCH) + koff);
#pragma unroll
            for (int mt = 0; mt < 2; mt++)
#pragma unroll
                for (int nb = 0; nb < 2; nb++) {
                    mma_bf16(acc[mt][nb * 2 + 0], a[mt], bh[nb][0], bh[nb][2]);
                    mma_bf16(acc[mt][nb * 2 + 1], a[mt], bh[nb][1], bh[nb][3]);
                }
        }

        // ---- epilogue: bias + relu + direct float2 stores ----
        const int rbase = t * 64 + wm * 32 + (lid >> 2);
        const int cbase = wn * 32 + (lid & 3) * 2;
#pragma unroll
        for (int mt = 0; mt < 2; mt++) {
#pragma unroll
            for (int nt = 0; nt < 4; nt++) {
                const int c = cbase + nt * 8;
                float2 v0, v1;
                v0.x = fmaxf(acc[mt][nt][0] + be[nt], 0.0f);
                v0.y = fmaxf(acc[mt][nt][1] + bo[nt], 0.0f);
                v1.x = fmaxf(acc[mt][nt][2] + be[nt], 0.0f);
                v1.y = fmaxf(acc[mt][nt][3] + bo[nt], 0.0f);
                const size_t r0 = (size_t)(rbase + mt * 16);
                *(float2*)(out + r0 * 256 + c)       = v0;
                *(float2*)(out + (r0 + 8) * 256 + c) = v1;
            }
        }
    }
}

extern "C" void kernel_launch(void* const* d_in, const int* in_sizes, int n_in,
                              void* d_out, int out_size)
{
    const float* qpos  = (const float*)d_in[0];
    const float* qdir  = (const float*)d_in[1];
    const float* qab   = (const float*)d_in[2];
    const float* qcar  = (const float*)d_in[3];
    const float* qst   = (const float*)d_in[4];
    const float* apos  = (const float*)d_in[5];
    const float* adir  = (const float*)d_in[6];
    const float* aab   = (const float*)d_in[7];
    const float* acar  = (const float*)d_in[8];
    const float* ast   = (const float*)d_in[9];
    const int*   color = (const int*)  d_in[10];
    const float* W     = (const float*)d_in[11];
    const float* bias  = (const float*)d_in[12];
    float* out = (float*)d_out;

    w_split<<<128, 256>>>(W);

    cudaFuncSetAttribute(mg_enc_hmma,
                         cudaFuncAttributeMaxDynamicSharedMemorySize, SMEM_BYTES);
    mg_enc_hmma<<<GRID, NTHREADS, SMEM_BYTES>>>(
        qpos, qdir, qab, qcar, qst,
        apos, adir, aab, acar, ast,
        color, bias, out);
}

// round 8
// speedup vs baseline: 1.8157x; 1.6923x over previous
#include <cuda_runtime.h>
#include <cuda_bf16.h>
#include <cstdint>

// MultiGridAgentEncoder: fused slot-gather + relu(x @ W + b)
// R8: warp-specialized persistent kernel. 8 producer warps gather/scatter tile t+1
// while 8 consumer warps run 3-pass split-bf16 HMMA on tile t. Double-buffered A,
// B resident in smem for all tiles, named-barrier handoff.

#define NTHREADS 512
#define GRID     148
#define NTILES   2048
#define PITCH    272          // bytes per K-row (128 bf16 + 16B pad), ldmatrix conflict-free
#define A_BYTES  17408        // 64 rows * 272

// smem byte offsets
#define SM_A0_HI 0
#define SM_A0_LO 17408
#define SM_A1_HI 34816
#define SM_A1_LO 52224
#define SM_B_HI  69632        // 256*272 = 69632, ends 139264
#define SM_B_LO  139264       // ends 208896
#define SM_SLOT  208896       // 2 bufs * 8*64 bytes = 1024, ends 209920
#define SMEM_BYTES 209920

// Pre-split W (filled once by w_split): [n][k] bf16, k padded to 128
__device__ __nv_bfloat16 g_Whi[256 * 128];
__device__ __nv_bfloat16 g_Wlo[256 * 128];

__global__ void w_split(const float* __restrict__ W) {
    const int k = blockIdx.x;        // 0..127
    const int n = threadIdx.x;       // 0..255
    float w = (k < 117) ? W[k * 256 + n] : 0.0f;
    __nv_bfloat16 h = __float2bfloat16(w);
    g_Whi[n * 128 + k] = h;
    g_Wlo[n * 128 + k] = __float2bfloat16(w - __bfloat162float(h));
}

static __device__ __forceinline__ uint32_t smem_u32(const void* p) {
    uint32_t a;
    asm("{ .reg .u64 t; cvta.to.shared.u64 t, %1; cvt.u32.u64 %0, t; }" : "=r"(a) : "l"(p));
    return a;
}
static __device__ __forceinline__ void bar_sync(int id, int cnt) {
    asm volatile("bar.sync %0, %1;" :: "r"(id), "r"(cnt) : "memory");
}
static __device__ __forceinline__ void bar_arrive(int id, int cnt) {
    asm volatile("bar.arrive %0, %1;" :: "r"(id), "r"(cnt) : "memory");
}
static __device__ __forceinline__ void ldsm_x4(uint32_t& r0, uint32_t& r1, uint32_t& r2,
                                               uint32_t& r3, uint32_t addr) {
    asm volatile("ldmatrix.sync.aligned.m8n8.x4.shared.b16 {%0,%1,%2,%3}, [%4];"
                 : "=r"(r0), "=r"(r1), "=r"(r2), "=r"(r3) : "r"(addr));
}
static __device__ __forceinline__ void mma_bf16(float* c, const uint32_t* a,
                                                uint32_t b0, uint32_t b1) {
    asm volatile(
        "mma.sync.aligned.m16n8k16.row.col.f32.bf16.bf16.f32 "
        "{%0,%1,%2,%3}, {%4,%5,%6,%7}, {%8,%9}, {%0,%1,%2,%3};"
        : "+f"(c[0]), "+f"(c[1]), "+f"(c[2]), "+f"(c[3])
        : "r"(a[0]), "r"(a[1]), "r"(a[2]), "r"(a[3]), "r"(b0), "r"(b1));
}
static __device__ __forceinline__ void splitw(float v, __nv_bfloat16& h, __nv_bfloat16& l) {
    h = __float2bfloat16(v);
    l = __float2bfloat16(v - __bfloat162float(h));
}
// write 13 features (hi/lo split) for one A row starting at k0
static __device__ __forceinline__ void write13(char* ah, char* al, int k0, const float* f) {
#pragma unroll
    for (int j = 0; j < 13; j++) {
        __nv_bfloat16 h, l; splitw(f[j], h, l);
        *(__nv_bfloat16*)(ah + (k0 + j) * 2) = h;
        *(__nv_bfloat16*)(al + (k0 + j) * 2) = l;
    }
}

__global__ __launch_bounds__(512, 1)
void mg_enc_ws(const float* __restrict__ qpos, const float* __restrict__ qdir,
               const float* __restrict__ qab,  const float* __restrict__ qcar,
               const float* __restrict__ qst,
               const float* __restrict__ apos, const float* __restrict__ adir,
               const float* __restrict__ aab,  const float* __restrict__ acar,
               const float* __restrict__ ast,
               const int*   __restrict__ color,
               const float* __restrict__ bias,
               float* __restrict__ out)
{
    extern __shared__ __align__(128) char smem[];
    const uint32_t sbase = smem_u32(smem);
    const int tid = threadIdx.x;

    if (tid >= 256) {
        // ======================= PRODUCER (warps 8..15) =======================
        const int tp = tid - 256;

        // zero-pad K rows 117..127 in all 4 A buffers (done once)
        for (int idx = tp; idx < 64 * 11; idx += 256) {
            const int r = idx / 11, kk = 117 + idx % 11;
            const uint32_t o = r * PITCH + kk * 2;
            *(__nv_bfloat16*)(smem + SM_A0_HI + o) = __nv_bfloat16(0.0f);
            *(__nv_bfloat16*)(smem + SM_A0_LO + o) = __nv_bfloat16(0.0f);
            *(__nv_bfloat16*)(smem + SM_A1_HI + o) = __nv_bfloat16(0.0f);
            *(__nv_bfloat16*)(smem + SM_A1_LO + o) = __nv_bfloat16(0.0f);
        }

        int t = blockIdx.x;
        int4 c0, c1, c2, c3;
        if (tp < 64) {
            const int4* cp = (const int4*)(color + (size_t)(t * 64 + tp) * 16);
            c0 = cp[0]; c1 = cp[1]; c2 = cp[2]; c3 = cp[3];
        }

        for (int it = 0; t < NTILES; it++, t += GRID) {
            const int buf = it & 1;
            if (it >= 2) bar_sync(3 + buf, 512);              // wait buf free

            signed char* slotb = (signed char*)(smem + SM_SLOT) + buf * 512;
            if (tp < 64) {
                int cols[16] = { c0.x, c0.y, c0.z, c0.w, c1.x, c1.y, c1.z, c1.w,
                                 c2.x, c2.y, c2.z, c2.w, c3.x, c3.y, c3.z, c3.w };
                signed char sa[8];
#pragma unroll
                for (int s = 0; s < 8; s++) sa[s] = -1;
                int sg = 0, sy = 0;
#pragma unroll
                for (int n = 0; n < 16; n++) {
                    int c = cols[n];
                    if (c == 5) { if (sg < 4) sa[sg] = (signed char)n; sg++; }
                    else if (c == 4) { if (sy < 4) sa[4 + sy] = (signed char)n; sy++; }
                }
#pragma unroll
                for (int s = 0; s < 8; s++) slotb[s * 64 + tp] = sa[s];
            }
            bar_sync(5, 256);                                  // producers: slots visible

            // prefetch next tile's color rows
            const int tn = t + GRID;
            if (tp < 64 && tn < NTILES) {
                const int4* cp = (const int4*)(color + (size_t)(tn * 64 + tp) * 16);
                c0 = cp[0]; c1 = cp[1]; c2 = cp[2]; c3 = cp[3];
            }

            char* const ahB = smem + (buf ? SM_A1_HI : SM_A0_HI);
            char* const alB = smem + (buf ? SM_A1_LO : SM_A0_LO);
            const int row0 = t * 64;

            // query features -> k 0..12 (64 threads, one per row)
            if (tp < 64) {
                const size_t row = (size_t)(row0 + tp);
                float f[13];
                *(float2*)(f + 0) = *(const float2*)(qpos + row * 2);
                *(float4*)(f + 2) = *(const float4*)(qdir + row * 4);
                *(float2*)(f + 6) = *(const float2*)(qab  + row * 2);
                *(float2*)(f + 8) = *(const float2*)(qcar + row * 2);
                f[10] = qst[row * 3 + 0]; f[11] = qst[row * 3 + 1]; f[12] = qst[row * 3 + 2];
                write13(ahB + tp * PITCH, alB + tp * PITCH, 0, f);
            }

            // agent gather: unit = (row, slot); 2 units per thread
#pragma unroll
            for (int uu = 0; uu < 2; uu++) {
                const int u = tp * 2 + uu;
                const int r = u >> 3, s = u & 7;
                const int a = (int)slotb[s * 64 + r];
                float f[13];
                if (a >= 0) {
                    const size_t base = (size_t)(row0 + r) * 16 + a;
                    *(float2*)(f + 0) = *(const float2*)(apos + base * 2);
                    *(float4*)(f + 2) = *(const float4*)(adir + base * 4);
                    *(float2*)(f + 6) = *(const float2*)(aab  + base * 2);
                    *(float2*)(f + 8) = *(const float2*)(acar + base * 2);
                    f[10] = ast[base * 3 + 0]; f[11] = ast[base * 3 + 1]; f[12] = ast[base * 3 + 2];
                } else {
#pragma unroll
                    for (int j = 0; j < 13; j++) f[j] = 0.0f;
                }
                write13(ahB + r * PITCH, alB + r * PITCH, 13 + s * 13, f);
            }
            bar_arrive(1 + buf, 512);                          // A[buf] ready
        }
    } else {
        // ======================= CONSUMER (warps 0..7) =======================
        const int wid = tid >> 5, lid = tid & 31;

        // B tiles: copy pre-split bf16 W into smem (once)
#pragma unroll
        for (int it = 0; it < 16; it++) {
            const int idx = it * 256 + tid;
            const int n = idx >> 4, c = idx & 15;
            *(uint4*)(smem + SM_B_HI + n * PITCH + c * 16) =
                *(const uint4*)((const char*)g_Whi + n * 256 + c * 16);
            *(uint4*)(smem + SM_B_LO + n * PITCH + c * 16) =
                *(const uint4*)((const char*)g_Wlo + n * 256 + c * 16);
        }

        const int wm = wid >> 2, wn = wid & 3;   // 2 x 4 warp grid, warp tile 32x64
        const uint32_t lrow = lid & 15, lhalf = (uint32_t)lid >> 4;
        const uint32_t a_lane = (wm * 32 + lrow) * PITCH + lhalf * 16;
        const uint32_t b_lane = (wn * 64 + lrow) * PITCH + lhalf * 16;
        const uint32_t BHb = sbase + SM_B_HI + b_lane;
        const uint32_t BLb = sbase + SM_B_LO + b_lane;

        float be[8], bo[8];
#pragma unroll
        for (int nt = 0; nt < 8; nt++) {
            const int c = wn * 64 + (lid & 3) * 2 + nt * 8;
            be[nt] = bias[c];
            bo[nt] = bias[c + 1];
        }

        int t = blockIdx.x;
        for (int it = 0; t < NTILES; it++, t += GRID) {
            const int buf = it & 1;
            bar_sync(1 + buf, 512);                            // wait A[buf] ready

            const uint32_t AHb = sbase + (buf ? SM_A1_HI : SM_A0_HI) + a_lane;
            const uint32_t ALb = sbase + (buf ? SM_A1_LO : SM_A0_LO) + a_lane;

            float acc[2][8][4];
#pragma unroll
            for (int mt = 0; mt < 2; mt++)
#pragma unroll
                for (int nt = 0; nt < 8; nt++)
#pragma unroll
                    for (int e = 0; e < 4; e++) acc[mt][nt][e] = 0.0f;

            const uint32_t passA[3] = { AHb, AHb, ALb };
            const uint32_t passB[3] = { BHb, BLb, BHb };
#pragma unroll
            for (int pass = 0; pass < 3; pass++) {
                const uint32_t Ab = passA[pass];
                const uint32_t Bb = passB[pass];
#pragma unroll 4
                for (int ks = 0; ks < 8; ks++) {
                    const uint32_t koff = ks * 32;
                    uint32_t a[2][4];
#pragma unroll
                    for (int mt = 0; mt < 2; mt++)
                        ldsm_x4(a[mt][0], a[mt][1], a[mt][2], a[mt][3],
                                Ab + mt * (16 * PITCH) + koff);
                    uint32_t b[4][4];
#pragma unroll
                    for (int nb = 0; nb < 4; nb++)
                        ldsm_x4(b[nb][0], b[nb][1], b[nb][2], b[nb][3],
                                Bb + nb * (16 * PITCH) + koff);
#pragma unroll
                    for (int mt = 0; mt < 2; mt++)
#pragma unroll
                        for (int nb = 0; nb < 4; nb++) {
                            mma_bf16(acc[mt][nb * 2 + 0], a[mt], b[nb][0], b[nb][2]);
                            mma_bf16(acc[mt][nb * 2 + 1], a[mt], b[nb][1], b[nb][3]);
                        }
                }
            }
            bar_arrive(3 + buf, 512);                          // A[buf] free

            // epilogue: bias + relu + direct float2 stores (overlaps producer)
            const int rbase = t * 64 + wm * 32 + (lid >> 2);
            const int cbase = wn * 64 + (lid & 3) * 2;
#pragma unroll
            for (int mt = 0; mt < 2; mt++) {
#pragma unroll
                for (int nt = 0; nt < 8; nt++) {
                    const int c = cbase + nt * 8;
                    float2 v0, v1;
                    v0.x = fmaxf(acc[mt][nt][0] + be[nt], 0.0f);
                    v0.y = fmaxf(acc[mt][nt][1] + bo[nt], 0.0f);
                    v1.x = fmaxf(acc[mt][nt][2] + be[nt], 0.0f);
                    v1.y = fmaxf(acc[mt][nt][3] + bo[nt], 0.0f);
                    const size_t r0 = (size_t)(rbase + mt * 16);
                    *(float2*)(out + r0 * 256 + c)       = v0;
                    *(float2*)(out + (r0 + 8) * 256 + c) = v1;
                }
            }
        }
    }
}

extern "C" void kernel_launch(void* const* d_in, const int* in_sizes, int n_in,
                              void* d_out, int out_size)
{
    const float* qpos  = (const float*)d_in[0];
    const float* qdir  = (const float*)d_in[1];
    const float* qab   = (const float*)d_in[2];
    const float* qcar  = (const float*)d_in[3];
    const float* qst   = (const float*)d_in[4];
    const float* apos  = (const float*)d_in[5];
    const float* adir  = (const float*)d_in[6];
    const float* aab   = (const float*)d_in[7];
    const float* acar  = (const float*)d_in[8];
    const float* ast   = (const float*)d_in[9];
    const int*   color = (const int*)  d_in[10];
    const float* W     = (const float*)d_in[11];
    const float* bias  = (const float*)d_in[12];
    float* out = (float*)d_out;

    w_split<<<128, 256>>>(W);

    cudaFuncSetAttribute(mg_enc_ws,
                         cudaFuncAttributeMaxDynamicSharedMemorySize, SMEM_BYTES);
    mg_enc_ws<<<GRID, NTHREADS, SMEM_BYTES>>>(
        qpos, qdir, qab, qcar, qst,
        apos, adir, aab, acar, ast,
        color, bias, out);
}